// round 1
// baseline (speedup 1.0000x reference)
#include <cuda_runtime.h>
#include <math.h>

// ---------------- problem constants ----------------
#define B_     2
#define I_     2048
#define J_     2048
#define DIM_   1024
#define H_     16
#define DH_    64
#define INNER_ 1024
#define EPS_   1e-5f
#define SCALE_ 0.125f   // DH^-0.5

// ---------------- scratch (device globals; allocation-free) ----------------
__device__ float g_xn [B_ * I_ * DIM_];      // 16 MB
__device__ float g_cn [B_ * J_ * DIM_];      // 16 MB
__device__ float g_qk [B_ * I_ * INNER_];    // 16 MB
__device__ float g_cqk[B_ * J_ * INNER_];    // 16 MB
__device__ float g_v  [B_ * I_ * INNER_];    // 16 MB
__device__ float g_cv [B_ * J_ * INNER_];    // 16 MB
__device__ float g_sim  [134217728];         // [B,H,I,J] 512 MB
__device__ float g_attn [134217728];         // head-mixed row-softmax attn
__device__ float g_cattn[134217728];         // head-mixed col-softmax attn
__device__ float g_rm[B_ * H_ * I_];         // row max
__device__ float g_rs[B_ * H_ * I_];         // row 1/sum
__device__ float g_cm[B_ * H_ * J_];         // col max
__device__ float g_cs[B_ * H_ * J_];         // col 1/sum
__device__ float g_o1[B_ * I_ * INNER_];     // merged-head out      16 MB
__device__ float g_o2[B_ * J_ * INNER_];     // merged-head ctx_out  16 MB

// ---------------- LayerNorm (one block per row, DIM=1024, 256 thr) -------
__global__ void ln_kernel(const float* __restrict__ x,
                          const float* __restrict__ gw,
                          const float* __restrict__ bw,
                          float* __restrict__ out) {
    int row = blockIdx.x;
    const float* xr = x + (size_t)row * DIM_;
    float* orow = out + (size_t)row * DIM_;
    int t = threadIdx.x;

    float v[4]; float s = 0.f, sq = 0.f;
#pragma unroll
    for (int k = 0; k < 4; k++) {
        v[k] = xr[t + 256 * k];
        s += v[k]; sq += v[k] * v[k];
    }
    __shared__ float sh[64];
#pragma unroll
    for (int o = 16; o > 0; o >>= 1) {
        s  += __shfl_down_sync(0xffffffffu, s,  o);
        sq += __shfl_down_sync(0xffffffffu, sq, o);
    }
    if ((t & 31) == 0) { sh[t >> 5] = s; sh[32 + (t >> 5)] = sq; }
    __syncthreads();
    if (t < 32) {
        float a  = (t < 8) ? sh[t]      : 0.f;
        float b2 = (t < 8) ? sh[32 + t] : 0.f;
#pragma unroll
        for (int o = 4; o > 0; o >>= 1) {
            a  += __shfl_down_sync(0xffffffffu, a,  o);
            b2 += __shfl_down_sync(0xffffffffu, b2, o);
        }
        if (t == 0) { sh[0] = a; sh[1] = b2; }
    }
    __syncthreads();
    float mu   = sh[0] * (1.f / DIM_);
    float var  = sh[1] * (1.f / DIM_) - mu * mu;
    float rstd = rsqrtf(var + EPS_);
#pragma unroll
    for (int k = 0; k < 4; k++) {
        int c = t + 256 * k;
        orow[c] = (v[k] - mu) * rstd * gw[c] + bw[c];
    }
}

// ---------------- generic 64x64x16 fp32 GEMM tile body --------------------
// ATRANS=false: A is [M,K] row-major (lda=K-ish). ATRANS=true: A is [K,M].
// BTRANS=false: B is [K,N].                       BTRANS=true: B is [N,K].
// C[M,N] = alpha * A(.T) @ B(.T) (+bias). M,N tiles of 64, K mult of 16.
template <bool ATRANS, bool BTRANS>
__device__ __forceinline__ void gemm_tile(const float* __restrict__ A, int lda,
                                          const float* __restrict__ Bm, int ldb,
                                          float* __restrict__ C, int ldc,
                                          int K, const float* __restrict__ bias,
                                          float alpha) {
    const int m0 = blockIdx.y * 64;
    const int n0 = blockIdx.x * 64;
    __shared__ float As[16][65];
    __shared__ float Bs[16][65];
    const int t  = threadIdx.x;
    const int tx = t & 15, ty = t >> 4;

    float acc[4][4] = {};

    for (int k0 = 0; k0 < K; k0 += 16) {
        if (!ATRANS) {
            int ar = t >> 4, ac = t & 15;
#pragma unroll
            for (int r = 0; r < 4; r++)
                As[ac][ar + 16 * r] =
                    A[(size_t)(m0 + ar + 16 * r) * lda + k0 + ac];
        } else {
            int kr = t >> 6, mc = t & 63;
#pragma unroll
            for (int r = 0; r < 4; r++)
                As[kr + 4 * r][mc] =
                    A[(size_t)(k0 + kr + 4 * r) * lda + m0 + mc];
        }
        if (!BTRANS) {
            int kr = t >> 6, nc = t & 63;
#pragma unroll
            for (int r = 0; r < 4; r++)
                Bs[kr + 4 * r][nc] =
                    Bm[(size_t)(k0 + kr + 4 * r) * ldb + n0 + nc];
        } else {
            int nr = t >> 4, kc = t & 15;
#pragma unroll
            for (int r = 0; r < 4; r++)
                Bs[kc][nr + 16 * r] =
                    Bm[(size_t)(n0 + nr + 16 * r) * ldb + k0 + kc];
        }
        __syncthreads();
#pragma unroll
        for (int kk = 0; kk < 16; kk++) {
            float a[4], b[4];
#pragma unroll
            for (int u = 0; u < 4; u++) a[u] = As[kk][ty * 4 + u];
#pragma unroll
            for (int v2 = 0; v2 < 4; v2++) b[v2] = Bs[kk][tx * 4 + v2];
#pragma unroll
            for (int u = 0; u < 4; u++)
#pragma unroll
                for (int v2 = 0; v2 < 4; v2++) acc[u][v2] += a[u] * b[v2];
        }
        __syncthreads();
    }

#pragma unroll
    for (int u = 0; u < 4; u++) {
        int m = m0 + ty * 4 + u;
        float4 r;
        r.x = acc[u][0] * alpha;
        r.y = acc[u][1] * alpha;
        r.z = acc[u][2] * alpha;
        r.w = acc[u][3] * alpha;
        if (bias) {
            int n = n0 + tx * 4;
            r.x += bias[n + 0]; r.y += bias[n + 1];
            r.z += bias[n + 2]; r.w += bias[n + 3];
        }
        *(float4*)(C + (size_t)m * ldc + n0 + tx * 4) = r;
    }
}

// projections and output projections: [M,1024]@[1024,1024](+bias)
__global__ void k_proj(const float* __restrict__ A, const float* __restrict__ W,
                       const float* __restrict__ bias, float* __restrict__ C) {
    gemm_tile<false, false>(A, 1024, W, 1024, C, 1024, 1024, bias, 1.0f);
}

// sim: per (b,h): C[i,j] = scale * sum_d Q[i,d] * K[j,d]
__global__ void k_sim() {
    int z = blockIdx.z, b = z >> 4, h = z & 15;
    gemm_tile<false, true>(g_qk  + (size_t)b * I_ * INNER_ + h * DH_, INNER_,
                           g_cqk + (size_t)b * J_ * INNER_ + h * DH_, INNER_,
                           g_sim + (size_t)z * I_ * J_, J_,
                           DH_, nullptr, SCALE_);
}

// out: per (b,h): C[i,d] = sum_j attn[i,j] * ctx_v[j,d]  (write merged heads)
__global__ void k_av() {
    int z = blockIdx.z, b = z >> 4, h = z & 15;
    gemm_tile<false, false>(g_attn + (size_t)z * I_ * J_, J_,
                            g_cv + (size_t)b * J_ * INNER_ + h * DH_, INNER_,
                            g_o1 + (size_t)b * I_ * INNER_ + h * DH_, INNER_,
                            J_, nullptr, 1.0f);
}

// ctx_out: per (b,h): C[j,d] = sum_i cattn[i,j] * v[i,d]  (A transposed)
__global__ void k_avt() {
    int z = blockIdx.z, b = z >> 4, h = z & 15;
    gemm_tile<true, false>(g_cattn + (size_t)z * I_ * J_, J_,
                           g_v  + (size_t)b * I_ * INNER_ + h * DH_, INNER_,
                           g_o2 + (size_t)b * J_ * INNER_ + h * DH_, INNER_,
                           I_, nullptr, 1.0f);
}

// ---------------- row stats: per (b,h,i) max & 1/sumexp over j ------------
__global__ void rowstat_kernel() {
    size_t row = blockIdx.x;                 // (b*H+h)*I + i
    const float* sr = g_sim + row * (size_t)J_;
    int t = threadIdx.x;
    float v[8]; float mx = -1e30f;
#pragma unroll
    for (int k = 0; k < 8; k++) { v[k] = sr[t + 256 * k]; mx = fmaxf(mx, v[k]); }
    __shared__ float sh[8];
    __shared__ float smax;
#pragma unroll
    for (int o = 16; o > 0; o >>= 1)
        mx = fmaxf(mx, __shfl_xor_sync(0xffffffffu, mx, o));
    if ((t & 31) == 0) sh[t >> 5] = mx;
    __syncthreads();
    if (t == 0) {
        float m = sh[0];
        for (int q = 1; q < 8; q++) m = fmaxf(m, sh[q]);
        smax = m;
    }
    __syncthreads();
    mx = smax;
    float s = 0.f;
#pragma unroll
    for (int k = 0; k < 8; k++) s += __expf(v[k] - mx);
#pragma unroll
    for (int o = 16; o > 0; o >>= 1)
        s += __shfl_xor_sync(0xffffffffu, s, o);
    if ((t & 31) == 0) sh[t >> 5] = s;
    __syncthreads();
    if (t == 0) {
        float a = 0.f;
        for (int q = 0; q < 8; q++) a += sh[q];
        g_rm[row] = mx;
        g_rs[row] = 1.f / a;
    }
}

// ---------------- col stats: per (b,h,j) max & 1/sumexp over i ------------
// block = 32 cols x 8 partials, online max/sum merge
__global__ void colstat_kernel() {
    int z  = blockIdx.y;                     // b*H+h
    int j0 = blockIdx.x * 32;
    const float* S = g_sim + (size_t)z * I_ * J_;
    int t = threadIdx.x;
    int c = t & 31, p = t >> 5;              // col, partial id

    float m = -1e30f, s = 0.f;
    for (int i = p; i < I_; i += 8) {
        float x = S[(size_t)i * J_ + j0 + c];
        float nm = fmaxf(m, x);
        s = s * __expf(m - nm) + __expf(x - nm);
        m = nm;
    }
    __shared__ float shm[8][33], shs[8][33];
    shm[p][c] = m; shs[p][c] = s;
    __syncthreads();
    if (p == 0) {
        float M = m, Sv = s;
#pragma unroll
        for (int q = 1; q < 8; q++) {
            float m2 = shm[q][c], s2 = shs[q][c];
            float nm = fmaxf(M, m2);
            Sv = Sv * __expf(M - nm) + s2 * __expf(m2 - nm);
            M = nm;
        }
        g_cm[(size_t)z * J_ + j0 + c] = M;
        g_cs[(size_t)z * J_ + j0 + c] = 1.f / Sv;
    }
}

// ------- fused softmax-normalize + talking-heads mix (both directions) ----
// one thread per (b,i,j): reads sim for all 16 heads, writes mixed attn & cattn
__global__ void mix_kernel(const float* __restrict__ thw,
                           const float* __restrict__ cthw) {
    int b = blockIdx.z;
    int i = blockIdx.y;
    int j = blockIdx.x * 256 + threadIdx.x;
    int t = threadIdx.x;

    __shared__ float wR[16][16], wC[16][16], rm[16], ri[16];
    wR[t >> 4][t & 15] = thw[t];
    wC[t >> 4][t & 15] = cthw[t];
    if (t < 16) {
        rm[t] = g_rm[((size_t)(b * H_ + t)) * I_ + i];
        ri[t] = g_rs[((size_t)(b * H_ + t)) * I_ + i];
    }
    __syncthreads();

    float pr[16], pc[16];
#pragma unroll
    for (int h = 0; h < 16; h++) {
        size_t zi = (size_t)(b * H_ + h);
        float sv = g_sim[(zi * I_ + i) * J_ + j];
        pr[h] = __expf(sv - rm[h]) * ri[h];
        float cm = g_cm[zi * J_ + j];
        float ci = g_cs[zi * J_ + j];
        pc[h] = __expf(sv - cm) * ci;
    }
#pragma unroll
    for (int g = 0; g < 16; g++) {
        float aR = 0.f, aC = 0.f;
#pragma unroll
        for (int h = 0; h < 16; h++) {
            aR += wR[g][h] * pr[h];
            aC += wC[g][h] * pc[h];
        }
        size_t zo = (size_t)(b * H_ + g);
        g_attn [(zo * I_ + i) * J_ + j] = aR;
        g_cattn[(zo * I_ + i) * J_ + j] = aC;
    }
}

// ---------------- launch ----------------
extern "C" void kernel_launch(void* const* d_in, const int* in_sizes, int n_in,
                              void* d_out, int out_size) {
    const float* x     = (const float*)d_in[0];
    const float* ctx   = (const float*)d_in[1];
    const float* ln_g  = (const float*)d_in[2];
    const float* ln_b  = (const float*)d_in[3];
    const float* cln_g = (const float*)d_in[4];
    const float* cln_b = (const float*)d_in[5];
    const float* W_qk  = (const float*)d_in[6];
    const float* W_cqk = (const float*)d_in[7];
    const float* W_v   = (const float*)d_in[8];
    const float* W_cv  = (const float*)d_in[9];
    const float* W_out = (const float*)d_in[10];
    const float* b_out = (const float*)d_in[11];
    const float* W_cout= (const float*)d_in[12];
    const float* b_cout= (const float*)d_in[13];
    const float* thw   = (const float*)d_in[14];
    const float* cthw  = (const float*)d_in[15];
    float* out = (float*)d_out;

    float *p_xn, *p_cn, *p_qk, *p_cqk, *p_v, *p_cv, *p_o1, *p_o2;
    cudaGetSymbolAddress((void**)&p_xn,  g_xn);
    cudaGetSymbolAddress((void**)&p_cn,  g_cn);
    cudaGetSymbolAddress((void**)&p_qk,  g_qk);
    cudaGetSymbolAddress((void**)&p_cqk, g_cqk);
    cudaGetSymbolAddress((void**)&p_v,   g_v);
    cudaGetSymbolAddress((void**)&p_cv,  g_cv);
    cudaGetSymbolAddress((void**)&p_o1,  g_o1);
    cudaGetSymbolAddress((void**)&p_o2,  g_o2);

    // 1) layernorms
    ln_kernel<<<B_ * I_, 256>>>(x,   ln_g,  ln_b,  p_xn);
    ln_kernel<<<B_ * J_, 256>>>(ctx, cln_g, cln_b, p_cn);

    // 2) projections: [4096,1024] @ [1024,1024]
    dim3 gp(DIM_ / 64, (B_ * I_) / 64);
    k_proj<<<gp, 256>>>(p_xn, W_qk,  nullptr, p_qk);
    k_proj<<<gp, 256>>>(p_xn, W_v,   nullptr, p_v);
    k_proj<<<gp, 256>>>(p_cn, W_cqk, nullptr, p_cqk);
    k_proj<<<gp, 256>>>(p_cn, W_cv,  nullptr, p_cv);

    // 3) sim = Q @ K^T * scale, batched over (b,h)
    k_sim<<<dim3(J_ / 64, I_ / 64, B_ * H_), 256>>>();

    // 4) softmax statistics (row over j, col over i)
    rowstat_kernel<<<B_ * H_ * I_, 256>>>();
    colstat_kernel<<<dim3(J_ / 32, B_ * H_), 256>>>();

    // 5) fused normalize + talking-heads mix, both directions
    mix_kernel<<<dim3(J_ / 256, I_, B_), 256>>>(thw, cthw);

    // 6) attention-weighted values (merged-head output layouts)
    k_av <<<dim3(1, I_ / 64, B_ * H_), 256>>>();
    k_avt<<<dim3(1, J_ / 64, B_ * H_), 256>>>();

    // 7) output projections straight into d_out (out first, then ctx_out)
    k_proj<<<gp, 256>>>(p_o1, W_out,  b_out,  out);
    k_proj<<<gp, 256>>>(p_o2, W_cout, b_cout, out + (size_t)B_ * I_ * DIM_);
}

// round 2
// speedup vs baseline: 1.3685x; 1.3685x over previous
#include <cuda_runtime.h>
#include <math.h>

// ---------------- problem constants ----------------
#define B_     2
#define I_     2048
#define J_     2048
#define DIM_   1024
#define H_     16
#define DH_    64
#define INNER_ 1024
#define EPS_   1e-5f
#define SCALE_ 0.125f   // DH^-0.5

// ---------------- scratch (device globals; allocation-free) ----------------
__device__ float g_xn [B_ * I_ * DIM_];
__device__ float g_cn [B_ * J_ * DIM_];
__device__ float g_qk [B_ * I_ * INNER_];
__device__ float g_cqk[B_ * J_ * INNER_];
__device__ float g_v  [B_ * I_ * INNER_];
__device__ float g_cv [B_ * J_ * INNER_];
__device__ float g_sim  [134217728];         // [B,H,I,J] 512 MB
__device__ float g_attn [134217728];
__device__ float g_cattn[134217728];
__device__ float g_rm[B_ * H_ * I_];
__device__ float g_rs[B_ * H_ * I_];
__device__ float g_cm[B_ * H_ * J_];
__device__ float g_cs[B_ * H_ * J_];
__device__ float g_o1[B_ * I_ * INNER_];
__device__ float g_o2[B_ * J_ * INNER_];

// ---------------- LayerNorm ----------------
__global__ void ln_kernel(const float* __restrict__ x,
                          const float* __restrict__ gw,
                          const float* __restrict__ bw,
                          float* __restrict__ out) {
    int row = blockIdx.x;
    const float* xr = x + (size_t)row * DIM_;
    float* orow = out + (size_t)row * DIM_;
    int t = threadIdx.x;

    float v[4]; float s = 0.f, sq = 0.f;
#pragma unroll
    for (int k = 0; k < 4; k++) {
        v[k] = xr[t + 256 * k];
        s += v[k]; sq += v[k] * v[k];
    }
    __shared__ float sh[64];
#pragma unroll
    for (int o = 16; o > 0; o >>= 1) {
        s  += __shfl_down_sync(0xffffffffu, s,  o);
        sq += __shfl_down_sync(0xffffffffu, sq, o);
    }
    if ((t & 31) == 0) { sh[t >> 5] = s; sh[32 + (t >> 5)] = sq; }
    __syncthreads();
    if (t < 32) {
        float a  = (t < 8) ? sh[t]      : 0.f;
        float b2 = (t < 8) ? sh[32 + t] : 0.f;
#pragma unroll
        for (int o = 4; o > 0; o >>= 1) {
            a  += __shfl_down_sync(0xffffffffu, a,  o);
            b2 += __shfl_down_sync(0xffffffffu, b2, o);
        }
        if (t == 0) { sh[0] = a; sh[1] = b2; }
    }
    __syncthreads();
    float mu   = sh[0] * (1.f / DIM_);
    float var  = sh[1] * (1.f / DIM_) - mu * mu;
    float rstd = rsqrtf(var + EPS_);
#pragma unroll
    for (int k = 0; k < 4; k++) {
        int c = t + 256 * k;
        orow[c] = (v[k] - mu) * rstd * gw[c] + bw[c];
    }
}

// ======== 128xBN x16 double-buffered SGEMM, 256 threads, 8x(4*NS) /thr =====
// ATRANS=false: A[M,K] (element (m,k) at A[m*lda+k]); true: A[K,M] (A[k*lda+m])
// BTRANS=false: B[K,N] (B[k*ldb+n]); true: B[N,K] (B[n*ldb+k]; only BN=128)
template <int BN, bool ATRANS, bool BTRANS>
__device__ __forceinline__ void gemm_body(const float* __restrict__ A, int lda,
                                          const float* __restrict__ B, int ldb,
                                          float* __restrict__ C, int ldc,
                                          int K, const float* __restrict__ bias,
                                          float alpha) {
    constexpr int BM = 128, BK = 16;
    constexpr int NS = BN / 64;   // 2 for BN=128, 1 for BN=64
    const int m0 = blockIdx.y * BM;
    const int n0 = blockIdx.x * BN;
    const int t  = threadIdx.x;
    const int tx = t & 15;        // 0..15 -> n quads
    const int ty = t >> 4;        // 0..15 -> m quads

    __shared__ float As[2][BK][BM];
    __shared__ float Bs[2][BK][BN];

    float acc[2][NS][4][4];
#pragma unroll
    for (int a0 = 0; a0 < 2; a0++)
#pragma unroll
        for (int a1 = 0; a1 < NS; a1++)
#pragma unroll
            for (int a2 = 0; a2 < 4; a2++)
#pragma unroll
                for (int a3 = 0; a3 < 4; a3++) acc[a0][a1][a2][a3] = 0.f;

    float4 la0, la1, lb0, lb1;

    auto gload = [&](int k0) {
        if (!ATRANS) {
            int ar = t >> 1, ac = (t & 1) * 8;
            const float* p = A + (size_t)(m0 + ar) * lda + k0 + ac;
            la0 = *(const float4*)p;
            la1 = *(const float4*)(p + 4);
        } else {
            int kr = t >> 4, mc = (t & 15) * 8;
            const float* p = A + (size_t)(k0 + kr) * lda + m0 + mc;
            la0 = *(const float4*)p;
            la1 = *(const float4*)(p + 4);
        }
        if (!BTRANS) {
            if (NS == 2) {
                int kr = t >> 4, nc = (t & 15) * 8;
                const float* p = B + (size_t)(k0 + kr) * ldb + n0 + nc;
                lb0 = *(const float4*)p;
                lb1 = *(const float4*)(p + 4);
            } else {
                int kr = t >> 4, nc = (t & 15) * 4;
                lb0 = *(const float4*)(B + (size_t)(k0 + kr) * ldb + n0 + nc);
            }
        } else {
            int nr = t >> 1, kc = (t & 1) * 8;
            const float* p = B + (size_t)(n0 + nr) * ldb + k0 + kc;
            lb0 = *(const float4*)p;
            lb1 = *(const float4*)(p + 4);
        }
    };

    auto sstore = [&](int buf) {
        if (!ATRANS) {
            int ar = t >> 1, ac = (t & 1) * 8;
            As[buf][ac + 0][ar] = la0.x; As[buf][ac + 1][ar] = la0.y;
            As[buf][ac + 2][ar] = la0.z; As[buf][ac + 3][ar] = la0.w;
            As[buf][ac + 4][ar] = la1.x; As[buf][ac + 5][ar] = la1.y;
            As[buf][ac + 6][ar] = la1.z; As[buf][ac + 7][ar] = la1.w;
        } else {
            int kr = t >> 4, mc = (t & 15) * 8;
            *(float4*)&As[buf][kr][mc]     = la0;
            *(float4*)&As[buf][kr][mc + 4] = la1;
        }
        if (!BTRANS) {
            if (NS == 2) {
                int kr = t >> 4, nc = (t & 15) * 8;
                *(float4*)&Bs[buf][kr][nc]     = lb0;
                *(float4*)&Bs[buf][kr][nc + 4] = lb1;
            } else {
                int kr = t >> 4, nc = (t & 15) * 4;
                *(float4*)&Bs[buf][kr][nc] = lb0;
            }
        } else {
            int nr = t >> 1, kc = (t & 1) * 8;
            Bs[buf][kc + 0][nr] = lb0.x; Bs[buf][kc + 1][nr] = lb0.y;
            Bs[buf][kc + 2][nr] = lb0.z; Bs[buf][kc + 3][nr] = lb0.w;
            Bs[buf][kc + 4][nr] = lb1.x; Bs[buf][kc + 5][nr] = lb1.y;
            Bs[buf][kc + 6][nr] = lb1.z; Bs[buf][kc + 7][nr] = lb1.w;
        }
    };

    gload(0);
    sstore(0);
    __syncthreads();
    int buf = 0;

    for (int k0 = 0; k0 < K; k0 += BK) {
        bool nxt = (k0 + BK) < K;
        if (nxt) gload(k0 + BK);
#pragma unroll
        for (int kk = 0; kk < BK; kk++) {
            float4 a0 = *(const float4*)&As[buf][kk][ty * 4];
            float4 a1 = *(const float4*)&As[buf][kk][64 + ty * 4];
            float4 b0 = *(const float4*)&Bs[buf][kk][tx * 4];
            float av0[4] = {a0.x, a0.y, a0.z, a0.w};
            float av1[4] = {a1.x, a1.y, a1.z, a1.w};
            float bv0[4] = {b0.x, b0.y, b0.z, b0.w};
            float bv1[4];
            if (NS == 2) {
                float4 b1 = *(const float4*)&Bs[buf][kk][64 + tx * 4];
                bv1[0] = b1.x; bv1[1] = b1.y; bv1[2] = b1.z; bv1[3] = b1.w;
            }
#pragma unroll
            for (int u = 0; u < 4; u++)
#pragma unroll
                for (int v = 0; v < 4; v++) {
                    acc[0][0][u][v] += av0[u] * bv0[v];
                    acc[1][0][u][v] += av1[u] * bv0[v];
                    if (NS == 2) {
                        acc[0][1][u][v] += av0[u] * bv1[v];
                        acc[1][1][u][v] += av1[u] * bv1[v];
                    }
                }
        }
        if (nxt) {
            sstore(buf ^ 1);
            __syncthreads();
            buf ^= 1;
        }
    }

#pragma unroll
    for (int mh = 0; mh < 2; mh++)
#pragma unroll
        for (int u = 0; u < 4; u++) {
            int m = m0 + mh * 64 + ty * 4 + u;
#pragma unroll
            for (int nh = 0; nh < NS; nh++) {
                int n = n0 + nh * 64 + tx * 4;
                float4 r;
                r.x = acc[mh][nh][u][0] * alpha;
                r.y = acc[mh][nh][u][1] * alpha;
                r.z = acc[mh][nh][u][2] * alpha;
                r.w = acc[mh][nh][u][3] * alpha;
                if (bias) {
                    r.x += bias[n + 0]; r.y += bias[n + 1];
                    r.z += bias[n + 2]; r.w += bias[n + 3];
                }
                *(float4*)&C[(size_t)m * ldc + n] = r;
            }
        }
}

// projections / output projections: [M,1024] @ [1024,1024] (+bias)
__global__ void __launch_bounds__(256) k_proj(const float* __restrict__ A,
                                              const float* __restrict__ W,
                                              const float* __restrict__ bias,
                                              float* __restrict__ C) {
    gemm_body<128, false, false>(A, 1024, W, 1024, C, 1024, 1024, bias, 1.0f);
}

// sim: per (b,h): C[i,j] = scale * sum_d Q[i,d] * K[j,d]
__global__ void __launch_bounds__(256) k_sim() {
    int z = blockIdx.z, b = z >> 4, h = z & 15;
    gemm_body<128, false, true>(
        g_qk  + (size_t)b * I_ * INNER_ + h * DH_, INNER_,
        g_cqk + (size_t)b * J_ * INNER_ + h * DH_, INNER_,
        g_sim + (size_t)z * I_ * J_, J_, DH_, nullptr, SCALE_);
}

// out: per (b,h): C[i,d] = sum_j attn[i,j] * ctx_v[j,d]
__global__ void __launch_bounds__(256) k_av() {
    int z = blockIdx.z, b = z >> 4, h = z & 15;
    gemm_body<64, false, false>(
        g_attn + (size_t)z * I_ * J_, J_,
        g_cv + (size_t)b * J_ * INNER_ + h * DH_, INNER_,
        g_o1 + (size_t)b * I_ * INNER_ + h * DH_, INNER_,
        J_, nullptr, 1.0f);
}

// ctx_out: per (b,h): C[j,d] = sum_i cattn[i,j] * v[i,d]
__global__ void __launch_bounds__(256) k_avt() {
    int z = blockIdx.z, b = z >> 4, h = z & 15;
    gemm_body<64, true, false>(
        g_cattn + (size_t)z * I_ * J_, J_,
        g_v  + (size_t)b * I_ * INNER_ + h * DH_, INNER_,
        g_o2 + (size_t)b * J_ * INNER_ + h * DH_, INNER_,
        I_, nullptr, 1.0f);
}

// ---------------- row stats ----------------
__global__ void rowstat_kernel() {
    size_t row = blockIdx.x;
    const float* sr = g_sim + row * (size_t)J_;
    int t = threadIdx.x;
    float v[8]; float mx = -1e30f;
#pragma unroll
    for (int k = 0; k < 8; k++) { v[k] = sr[t + 256 * k]; mx = fmaxf(mx, v[k]); }
    __shared__ float sh[8];
    __shared__ float smax;
#pragma unroll
    for (int o = 16; o > 0; o >>= 1)
        mx = fmaxf(mx, __shfl_xor_sync(0xffffffffu, mx, o));
    if ((t & 31) == 0) sh[t >> 5] = mx;
    __syncthreads();
    if (t == 0) {
        float m = sh[0];
        for (int q = 1; q < 8; q++) m = fmaxf(m, sh[q]);
        smax = m;
    }
    __syncthreads();
    mx = smax;
    float s = 0.f;
#pragma unroll
    for (int k = 0; k < 8; k++) s += __expf(v[k] - mx);
#pragma unroll
    for (int o = 16; o > 0; o >>= 1)
        s += __shfl_xor_sync(0xffffffffu, s, o);
    if ((t & 31) == 0) sh[t >> 5] = s;
    __syncthreads();
    if (t == 0) {
        float a = 0.f;
        for (int q = 0; q < 8; q++) a += sh[q];
        g_rm[row] = mx;
        g_rs[row] = 1.f / a;
    }
}

// ---------------- col stats ----------------
__global__ void colstat_kernel() {
    int z  = blockIdx.y;
    int j0 = blockIdx.x * 32;
    const float* S = g_sim + (size_t)z * I_ * J_;
    int t = threadIdx.x;
    int c = t & 31, p = t >> 5;

    float m = -1e30f, s = 0.f;
    for (int i = p; i < I_; i += 8) {
        float x = S[(size_t)i * J_ + j0 + c];
        float nm = fmaxf(m, x);
        s = s * __expf(m - nm) + __expf(x - nm);
        m = nm;
    }
    __shared__ float shm[8][33], shs[8][33];
    shm[p][c] = m; shs[p][c] = s;
    __syncthreads();
    if (p == 0) {
        float M = m, Sv = s;
#pragma unroll
        for (int q = 1; q < 8; q++) {
            float m2 = shm[q][c], s2 = shs[q][c];
            float nm = fmaxf(M, m2);
            Sv = Sv * __expf(M - nm) + s2 * __expf(m2 - nm);
            M = nm;
        }
        g_cm[(size_t)z * J_ + j0 + c] = M;
        g_cs[(size_t)z * J_ + j0 + c] = 1.f / Sv;
    }
}

// ------- fused softmax-normalize + talking-heads mix (both directions) ----
__global__ void mix_kernel(const float* __restrict__ thw,
                           const float* __restrict__ cthw) {
    int b = blockIdx.z;
    int i = blockIdx.y;
    int j = blockIdx.x * 256 + threadIdx.x;
    int t = threadIdx.x;

    __shared__ float wR[16][16], wC[16][16], rm[16], ri[16];
    wR[t >> 4][t & 15] = thw[t];
    wC[t >> 4][t & 15] = cthw[t];
    if (t < 16) {
        rm[t] = g_rm[((size_t)(b * H_ + t)) * I_ + i];
        ri[t] = g_rs[((size_t)(b * H_ + t)) * I_ + i];
    }
    __syncthreads();

    float pr[16], pc[16];
#pragma unroll
    for (int h = 0; h < 16; h++) {
        size_t zi = (size_t)(b * H_ + h);
        float sv = g_sim[(zi * I_ + i) * J_ + j];
        pr[h] = __expf(sv - rm[h]) * ri[h];
        float cm = g_cm[zi * J_ + j];
        float ci = g_cs[zi * J_ + j];
        pc[h] = __expf(sv - cm) * ci;
    }
#pragma unroll
    for (int g = 0; g < 16; g++) {
        float aR = 0.f, aC = 0.f;
#pragma unroll
        for (int h = 0; h < 16; h++) {
            aR += wR[g][h] * pr[h];
            aC += wC[g][h] * pc[h];
        }
        size_t zo = (size_t)(b * H_ + g);
        g_attn [(zo * I_ + i) * J_ + j] = aR;
        g_cattn[(zo * I_ + i) * J_ + j] = aC;
    }
}

// ---------------- launch ----------------
extern "C" void kernel_launch(void* const* d_in, const int* in_sizes, int n_in,
                              void* d_out, int out_size) {
    const float* x     = (const float*)d_in[0];
    const float* ctx   = (const float*)d_in[1];
    const float* ln_g  = (const float*)d_in[2];
    const float* ln_b  = (const float*)d_in[3];
    const float* cln_g = (const float*)d_in[4];
    const float* cln_b = (const float*)d_in[5];
    const float* W_qk  = (const float*)d_in[6];
    const float* W_cqk = (const float*)d_in[7];
    const float* W_v   = (const float*)d_in[8];
    const float* W_cv  = (const float*)d_in[9];
    const float* W_out = (const float*)d_in[10];
    const float* b_out = (const float*)d_in[11];
    const float* W_cout= (const float*)d_in[12];
    const float* b_cout= (const float*)d_in[13];
    const float* thw   = (const float*)d_in[14];
    const float* cthw  = (const float*)d_in[15];
    float* out = (float*)d_out;

    float *p_xn, *p_cn, *p_qk, *p_cqk, *p_v, *p_cv, *p_o1, *p_o2;
    cudaGetSymbolAddress((void**)&p_xn,  g_xn);
    cudaGetSymbolAddress((void**)&p_cn,  g_cn);
    cudaGetSymbolAddress((void**)&p_qk,  g_qk);
    cudaGetSymbolAddress((void**)&p_cqk, g_cqk);
    cudaGetSymbolAddress((void**)&p_v,   g_v);
    cudaGetSymbolAddress((void**)&p_cv,  g_cv);
    cudaGetSymbolAddress((void**)&p_o1,  g_o1);
    cudaGetSymbolAddress((void**)&p_o2,  g_o2);

    // 1) layernorms
    ln_kernel<<<B_ * I_, 256>>>(x,   ln_g,  ln_b,  p_xn);
    ln_kernel<<<B_ * J_, 256>>>(ctx, cln_g, cln_b, p_cn);

    // 2) projections: [4096,1024] @ [1024,1024], 128x128 tiles
    dim3 gp(DIM_ / 128, (B_ * I_) / 128);
    k_proj<<<gp, 256>>>(p_xn, W_qk,  nullptr, p_qk);
    k_proj<<<gp, 256>>>(p_xn, W_v,   nullptr, p_v);
    k_proj<<<gp, 256>>>(p_cn, W_cqk, nullptr, p_cqk);
    k_proj<<<gp, 256>>>(p_cn, W_cv,  nullptr, p_cv);

    // 3) sim = Q @ K^T * scale, batched over (b,h)
    k_sim<<<dim3(J_ / 128, I_ / 128, B_ * H_), 256>>>();

    // 4) softmax statistics
    rowstat_kernel<<<B_ * H_ * I_, 256>>>();
    colstat_kernel<<<dim3(J_ / 32, B_ * H_), 256>>>();

    // 5) fused normalize + talking-heads mix
    mix_kernel<<<dim3(J_ / 256, I_, B_), 256>>>(thw, cthw);

    // 6) attention-weighted values
    k_av <<<dim3(1, I_ / 128, B_ * H_), 256>>>();
    k_avt<<<dim3(1, J_ / 128, B_ * H_), 256>>>();

    // 7) output projections straight into d_out
    k_proj<<<gp, 256>>>(p_o1, W_out,  b_out,  out);
    k_proj<<<gp, 256>>>(p_o2, W_cout, b_cout, out + (size_t)B_ * I_ * DIM_);
}